// round 1
// baseline (speedup 1.0000x reference)
#include <cuda_runtime.h>
#include <mma.h>

using namespace nvcuda;

#define BATCH 2
#define SEQ 4096
#define DIM 768
#define NH 12
#define HD 64
#define ROWS (BATCH*SEQ)

// Scratch (allocation-free rule: __device__ globals)
__device__ float g_Q[(size_t)BATCH*NH*SEQ*HD];
__device__ float g_K[(size_t)BATCH*NH*SEQ*HD];
__device__ float g_V[(size_t)BATCH*NH*SEQ*HD];
__device__ float g_AO[(size_t)ROWS*DIM];

typedef wmma::fragment<wmma::matrix_a, 16,16,8, wmma::precision::tf32, wmma::row_major> FragA;
typedef wmma::fragment<wmma::matrix_b, 16,16,8, wmma::precision::tf32, wmma::row_major> FragB;
typedef wmma::fragment<wmma::matrix_b, 16,16,8, wmma::precision::tf32, wmma::col_major> FragBT;
typedef wmma::fragment<wmma::accumulator, 16,16,8, float> FragC;

template <class F>
__device__ __forceinline__ void conv_tf32(F& f) {
#pragma unroll
    for (int i = 0; i < f.num_elements; i++) f.x[i] = wmma::__float_to_tf32(f.x[i]);
}

// ---------------------------------------------------------------------------
// Fused QKV projection: [8192,768] x 3*[768,768] + bias -> g_Q/g_K/g_V [B,H,S,64]
// ---------------------------------------------------------------------------
__global__ __launch_bounds__(256) void gemm_qkv_kernel(
    const float* __restrict__ X,
    const float* __restrict__ Wq, const float* __restrict__ bq,
    const float* __restrict__ Wk, const float* __restrict__ bk,
    const float* __restrict__ Wv, const float* __restrict__ bv)
{
    __shared__ float As[64*32];
    __shared__ float Bs[32*64];
    __shared__ float Cs[64*64];

    const int t = threadIdx.x;
    const int warp = t >> 5;
    const int wr = warp >> 1;          // 0..3  (16-row strip)
    const int wc = (warp & 1) * 2;     // 0 or 2 (two 16-col tiles)
    const int wsel = blockIdx.x / 12;
    const int n0 = (blockIdx.x % 12) * 64;
    const int m0 = blockIdx.y * 64;

    const float* W    = (wsel == 0) ? Wq : ((wsel == 1) ? Wk : Wv);
    const float* bias = (wsel == 0) ? bq : ((wsel == 1) ? bk : bv);
    float* dst        = (wsel == 0) ? g_Q : ((wsel == 1) ? g_K : g_V);

    FragC c0, c1;
    wmma::fill_fragment(c0, 0.f);
    wmma::fill_fragment(c1, 0.f);

    for (int k0 = 0; k0 < DIM; k0 += 32) {
        for (int i = t; i < 512; i += 256) {
            int r = i >> 3, c4 = (i & 7) * 4;
            *(float4*)(As + r*32 + c4) =
                *(const float4*)(X + (size_t)(m0 + r)*DIM + k0 + c4);
        }
        for (int i = t; i < 512; i += 256) {
            int r = i >> 4, c4 = (i & 15) * 4;
            *(float4*)(Bs + r*64 + c4) =
                *(const float4*)(W + (size_t)(k0 + r)*DIM + n0 + c4);
        }
        __syncthreads();
#pragma unroll
        for (int kk = 0; kk < 4; kk++) {
            FragA a; FragB b0, b1;
            wmma::load_matrix_sync(a, As + wr*16*32 + kk*8, 32);
            conv_tf32(a);
            wmma::load_matrix_sync(b0, Bs + kk*8*64 + wc*16, 64);
            conv_tf32(b0);
            wmma::load_matrix_sync(b1, Bs + kk*8*64 + (wc + 1)*16, 64);
            conv_tf32(b1);
            wmma::mma_sync(c0, a, b0, c0);
            wmma::mma_sync(c1, a, b1, c1);
        }
        __syncthreads();
    }

    wmma::store_matrix_sync(Cs + wr*16*64 + wc*16,       c0, 64, wmma::mem_row_major);
    wmma::store_matrix_sync(Cs + wr*16*64 + (wc + 1)*16, c1, 64, wmma::mem_row_major);
    __syncthreads();

    for (int i = t; i < 4096; i += 256) {
        int r = i >> 6, c = i & 63;
        int m = m0 + r, nn = n0 + c;
        float val = Cs[r*64 + c] + bias[nn];
        int bb = m >> 12;      // / SEQ
        int s  = m & 4095;
        int hh = nn >> 6;
        int d  = nn & 63;
        dst[((size_t)(bb*NH + hh)*SEQ + s)*HD + d] = val;
    }
}

// ---------------------------------------------------------------------------
// Flash attention: per (b,h,q-tile 64 rows), streaming online softmax.
// ---------------------------------------------------------------------------
#define SLD 68   // padded row stride for score/out tiles (multiple of 4)
#define ATTN_SMEM_FLOATS (4096*3 + 64*SLD*2 + 64*4 + 256)

__global__ __launch_bounds__(256) void attn_kernel()
{
    extern __shared__ float sm[];
    float* Qs     = sm;            // 64x64
    float* Ks     = sm + 4096;     // 64x64
    float* Vs     = sm + 8192;     // 64x64
    float* Ss     = sm + 12288;    // 64xSLD
    float* Os     = Ss + 64*SLD;   // 64xSLD
    float* mrow   = Os + 64*SLD;   // 64
    float* lrow   = mrow + 64;     // 64
    float* mnewS  = lrow + 64;     // 64
    float* alphaS = mnewS + 64;    // 64
    float* red    = alphaS + 64;   // 4*64

    const int t = threadIdx.x;
    const int warp = t >> 5;
    const int wr = warp >> 1;
    const int wc = (warp & 1) * 2;
    const int qt = blockIdx.x, h = blockIdx.y, b = blockIdx.z;

    const size_t headoff = ((size_t)(b*NH + h))*SEQ*HD;
    const float* Qg = g_Q + headoff + (size_t)qt*64*HD;
    const float* Kg = g_K + headoff;
    const float* Vg = g_V + headoff;
    const float scale = 0.125f;  // 1/sqrt(64)

    for (int i = t; i < 1024; i += 256) {
        int r = i >> 4, c4 = (i & 15) * 4;
        float4 v = *(const float4*)(Qg + r*HD + c4);
        v.x *= scale; v.y *= scale; v.z *= scale; v.w *= scale;
        *(float4*)(Qs + r*64 + c4) = v;
    }
    for (int i = t; i < 64*SLD; i += 256) Os[i] = 0.f;
    if (t < 64) { mrow[t] = -1e30f; lrow[t] = 0.f; }
    __syncthreads();

    for (int kt = 0; kt < SEQ/64; ++kt) {
        const float* Kt = Kg + (size_t)kt*64*HD;
        const float* Vt = Vg + (size_t)kt*64*HD;
        for (int i = t; i < 1024; i += 256) {
            int r = i >> 4, c4 = (i & 15) * 4;
            *(float4*)(Ks + r*64 + c4) = *(const float4*)(Kt + r*HD + c4);
            *(float4*)(Vs + r*64 + c4) = *(const float4*)(Vt + r*HD + c4);
        }
        __syncthreads();

        // S = Q * K^T  (K tile is [64 rows x 64 dims] -> B col_major = K^T)
        {
            FragC c0, c1;
            wmma::fill_fragment(c0, 0.f);
            wmma::fill_fragment(c1, 0.f);
#pragma unroll
            for (int kk = 0; kk < 8; kk++) {
                FragA a; FragBT b0, b1;
                wmma::load_matrix_sync(a, Qs + wr*16*64 + kk*8, 64);
                conv_tf32(a);
                wmma::load_matrix_sync(b0, Ks + wc*16*64 + kk*8, 64);
                conv_tf32(b0);
                wmma::load_matrix_sync(b1, Ks + (wc + 1)*16*64 + kk*8, 64);
                conv_tf32(b1);
                wmma::mma_sync(c0, a, b0, c0);
                wmma::mma_sync(c1, a, b1, c1);
            }
            wmma::store_matrix_sync(Ss + wr*16*SLD + wc*16,       c0, SLD, wmma::mem_row_major);
            wmma::store_matrix_sync(Ss + wr*16*SLD + (wc + 1)*16, c1, SLD, wmma::mem_row_major);
        }
        __syncthreads();

        // online softmax update
        {
            const int row = t & 63, qd = t >> 6;
            float* srow = Ss + row*SLD + qd*16;
            float lm = -1e30f;
#pragma unroll
            for (int j = 0; j < 16; j++) lm = fmaxf(lm, srow[j]);
            red[qd*64 + row] = lm;
            __syncthreads();
            if (t < 64) {
                float mo = mrow[t];
                float mx = fmaxf(fmaxf(red[t], red[64 + t]), fmaxf(red[128 + t], red[192 + t]));
                float mn = fmaxf(mo, mx);
                mnewS[t]  = mn;
                alphaS[t] = __expf(mo - mn);
                mrow[t]   = mn;
            }
            __syncthreads();
            float mn = mnewS[row];
            float al = alphaS[row];
            float* orow = Os + row*SLD + qd*16;
            float ps = 0.f;
#pragma unroll
            for (int j = 0; j < 16; j++) {
                float p = __expf(srow[j] - mn);
                srow[j] = p;
                ps += p;
                orow[j] *= al;
            }
            red[qd*64 + row] = ps;
            __syncthreads();
            if (t < 64)
                lrow[t] = lrow[t]*alphaS[t] + red[t] + red[64 + t] + red[128 + t] + red[192 + t];
        }

        // O += P * V
        {
            FragC c0, c1;
            wmma::load_matrix_sync(c0, Os + wr*16*SLD + wc*16,       SLD, wmma::mem_row_major);
            wmma::load_matrix_sync(c1, Os + wr*16*SLD + (wc + 1)*16, SLD, wmma::mem_row_major);
#pragma unroll
            for (int kk = 0; kk < 8; kk++) {
                FragA a; FragB b0, b1;
                wmma::load_matrix_sync(a, Ss + wr*16*SLD + kk*8, SLD);
                conv_tf32(a);
                wmma::load_matrix_sync(b0, Vs + kk*8*64 + wc*16, 64);
                conv_tf32(b0);
                wmma::load_matrix_sync(b1, Vs + kk*8*64 + (wc + 1)*16, 64);
                conv_tf32(b1);
                wmma::mma_sync(c0, a, b0, c0);
                wmma::mma_sync(c1, a, b1, c1);
            }
            wmma::store_matrix_sync(Os + wr*16*SLD + wc*16,       c0, SLD, wmma::mem_row_major);
            wmma::store_matrix_sync(Os + wr*16*SLD + (wc + 1)*16, c1, SLD, wmma::mem_row_major);
        }
        __syncthreads();
    }

    // normalize and write merged-head output [B,S,D]
    {
        const int row = t & 63, qd = t >> 6;
        float inv = 1.f / lrow[row];
        int s = qt*64 + row;
        float* dst = g_AO + ((size_t)b*SEQ + s)*DIM + h*64 + qd*16;
        float* orow = Os + row*SLD + qd*16;
#pragma unroll
        for (int j = 0; j < 16; j++) dst[j] = orow[j]*inv;
    }
}

// ---------------------------------------------------------------------------
// Output projection: g_AO [8192,768] x Wo [768,768] + bo -> d_out
// ---------------------------------------------------------------------------
__global__ __launch_bounds__(256) void gemm_o_kernel(
    const float* __restrict__ Wo, const float* __restrict__ bo,
    float* __restrict__ out)
{
    __shared__ float As[64*32];
    __shared__ float Bs[32*64];
    __shared__ float Cs[64*64];

    const int t = threadIdx.x;
    const int warp = t >> 5;
    const int wr = warp >> 1;
    const int wc = (warp & 1) * 2;
    const int n0 = blockIdx.x * 64;
    const int m0 = blockIdx.y * 64;
    const float* A = g_AO;

    FragC c0, c1;
    wmma::fill_fragment(c0, 0.f);
    wmma::fill_fragment(c1, 0.f);

    for (int k0 = 0; k0 < DIM; k0 += 32) {
        for (int i = t; i < 512; i += 256) {
            int r = i >> 3, c4 = (i & 7) * 4;
            *(float4*)(As + r*32 + c4) =
                *(const float4*)(A + (size_t)(m0 + r)*DIM + k0 + c4);
        }
        for (int i = t; i < 512; i += 256) {
            int r = i >> 4, c4 = (i & 15) * 4;
            *(float4*)(Bs + r*64 + c4) =
                *(const float4*)(Wo + (size_t)(k0 + r)*DIM + n0 + c4);
        }
        __syncthreads();
#pragma unroll
        for (int kk = 0; kk < 4; kk++) {
            FragA a; FragB b0, b1;
            wmma::load_matrix_sync(a, As + wr*16*32 + kk*8, 32);
            conv_tf32(a);
            wmma::load_matrix_sync(b0, Bs + kk*8*64 + wc*16, 64);
            conv_tf32(b0);
            wmma::load_matrix_sync(b1, Bs + kk*8*64 + (wc + 1)*16, 64);
            conv_tf32(b1);
            wmma::mma_sync(c0, a, b0, c0);
            wmma::mma_sync(c1, a, b1, c1);
        }
        __syncthreads();
    }

    wmma::store_matrix_sync(Cs + wr*16*64 + wc*16,       c0, 64, wmma::mem_row_major);
    wmma::store_matrix_sync(Cs + wr*16*64 + (wc + 1)*16, c1, 64, wmma::mem_row_major);
    __syncthreads();

    for (int i = t; i < 4096; i += 256) {
        int r = i >> 6, c = i & 63;
        int m = m0 + r, nn = n0 + c;
        out[(size_t)m*DIM + nn] = Cs[r*64 + c] + bo[nn];
    }
}

// ---------------------------------------------------------------------------
extern "C" void kernel_launch(void* const* d_in, const int* in_sizes, int n_in,
                              void* d_out, int out_size)
{
    (void)in_sizes; (void)n_in; (void)out_size;
    const float* x  = (const float*)d_in[0];
    const float* Wq = (const float*)d_in[1];
    const float* bq = (const float*)d_in[2];
    const float* Wk = (const float*)d_in[3];
    const float* bk = (const float*)d_in[4];
    const float* Wv = (const float*)d_in[5];
    const float* bv = (const float*)d_in[6];
    const float* Wo = (const float*)d_in[7];
    const float* bo = (const float*)d_in[8];
    float* out = (float*)d_out;

    cudaFuncSetAttribute(attn_kernel,
                         cudaFuncAttributeMaxDynamicSharedMemorySize,
                         ATTN_SMEM_FLOATS * (int)sizeof(float));

    gemm_qkv_kernel<<<dim3(36, 128), 256>>>(x, Wq, bq, Wk, bk, Wv, bv);
    attn_kernel<<<dim3(SEQ/64, NH, BATCH), 256, ATTN_SMEM_FLOATS * sizeof(float)>>>();
    gemm_o_kernel<<<dim3(12, 128), 256>>>(Wo, bo, out);
}

// round 2
// speedup vs baseline: 2.6082x; 2.6082x over previous
#include <cuda_runtime.h>
#include <mma.h>
#include <cstdint>

using namespace nvcuda;

#define BATCH 2
#define SEQ 4096
#define DIM 768
#define NH 12
#define HD 64
#define ROWS (BATCH*SEQ)

// Scratch (allocation-free rule: __device__ globals)
__device__ float g_Q[(size_t)BATCH*NH*SEQ*HD];
__device__ float g_K[(size_t)BATCH*NH*SEQ*HD];
__device__ float g_V[(size_t)BATCH*NH*SEQ*HD];
__device__ float g_AO[(size_t)ROWS*DIM];

typedef wmma::fragment<wmma::matrix_a, 16,16,8, wmma::precision::tf32, wmma::row_major> FragA;
typedef wmma::fragment<wmma::matrix_b, 16,16,8, wmma::precision::tf32, wmma::row_major> FragB;
typedef wmma::fragment<wmma::accumulator, 16,16,8, float> FragC;

template <class F>
__device__ __forceinline__ void conv_tf32(F& f) {
#pragma unroll
    for (int i = 0; i < f.num_elements; i++) f.x[i] = wmma::__float_to_tf32(f.x[i]);
}

// ---------------------------------------------------------------------------
// Fused QKV projection: [8192,768] x 3*[768,768] + bias -> g_Q/g_K/g_V [B,H,S,64]
// ---------------------------------------------------------------------------
__global__ __launch_bounds__(256) void gemm_qkv_kernel(
    const float* __restrict__ X,
    const float* __restrict__ Wq, const float* __restrict__ bq,
    const float* __restrict__ Wk, const float* __restrict__ bk,
    const float* __restrict__ Wv, const float* __restrict__ bv)
{
    __shared__ float As[64*32];
    __shared__ float Bs[32*64];
    __shared__ float Cs[64*64];

    const int t = threadIdx.x;
    const int warp = t >> 5;
    const int wr = warp >> 1;          // 0..3  (16-row strip)
    const int wc = (warp & 1) * 2;     // 0 or 2 (two 16-col tiles)
    const int wsel = blockIdx.x / 12;
    const int n0 = (blockIdx.x % 12) * 64;
    const int m0 = blockIdx.y * 64;

    const float* W    = (wsel == 0) ? Wq : ((wsel == 1) ? Wk : Wv);
    const float* bias = (wsel == 0) ? bq : ((wsel == 1) ? bk : bv);
    float* dst        = (wsel == 0) ? g_Q : ((wsel == 1) ? g_K : g_V);

    FragC c0, c1;
    wmma::fill_fragment(c0, 0.f);
    wmma::fill_fragment(c1, 0.f);

    for (int k0 = 0; k0 < DIM; k0 += 32) {
        for (int i = t; i < 512; i += 256) {
            int r = i >> 3, c4 = (i & 7) * 4;
            *(float4*)(As + r*32 + c4) =
                *(const float4*)(X + (size_t)(m0 + r)*DIM + k0 + c4);
        }
        for (int i = t; i < 512; i += 256) {
            int r = i >> 4, c4 = (i & 15) * 4;
            *(float4*)(Bs + r*64 + c4) =
                *(const float4*)(W + (size_t)(k0 + r)*DIM + n0 + c4);
        }
        __syncthreads();
#pragma unroll
        for (int kk = 0; kk < 4; kk++) {
            FragA a; FragB b0, b1;
            wmma::load_matrix_sync(a, As + wr*16*32 + kk*8, 32);
            conv_tf32(a);
            wmma::load_matrix_sync(b0, Bs + kk*8*64 + wc*16, 64);
            conv_tf32(b0);
            wmma::load_matrix_sync(b1, Bs + kk*8*64 + (wc + 1)*16, 64);
            conv_tf32(b1);
            wmma::mma_sync(c0, a, b0, c0);
            wmma::mma_sync(c1, a, b1, c1);
        }
        __syncthreads();
    }

    wmma::store_matrix_sync(Cs + wr*16*64 + wc*16,       c0, 64, wmma::mem_row_major);
    wmma::store_matrix_sync(Cs + wr*16*64 + (wc + 1)*16, c1, 64, wmma::mem_row_major);
    __syncthreads();

    for (int i = t; i < 4096; i += 256) {
        int r = i >> 6, c = i & 63;
        int m = m0 + r, nn = n0 + c;
        float val = Cs[r*64 + c] + bias[nn];
        int bb = m >> 12;      // / SEQ
        int s  = m & 4095;
        int hh = nn >> 6;
        int d  = nn & 63;
        dst[((size_t)(bb*NH + hh)*SEQ + s)*HD + d] = val;
    }
}

// ---------------------------------------------------------------------------
// Flash attention v2: register-resident mma.sync m16n8k8 tf32
//   CTA = 128 threads (4 warps), Q tile = 128 rows, K tile = 64 keys.
//   Each warp owns 32 q-rows (2 strips of 16). O accumulator, scores and
//   softmax all stay in registers. cp.async double-buffered K/V.
// ---------------------------------------------------------------------------
#define QSTRIDE 68
#define KSTRIDE 68
#define VSTRIDE 72
#define ATTN2_SMEM_BYTES ((128*QSTRIDE + 2*64*KSTRIDE + 2*64*VSTRIDE) * 4)

__device__ __forceinline__ unsigned f2tf(float f) {
    unsigned u;
    asm("cvt.rna.tf32.f32 %0, %1;" : "=r"(u) : "f"(f));
    return u;
}

__device__ __forceinline__ void mma8(float d[4], const unsigned a[4],
                                     unsigned b0, unsigned b1) {
    asm volatile(
        "mma.sync.aligned.m16n8k8.row.col.f32.tf32.tf32.f32 "
        "{%0,%1,%2,%3}, {%4,%5,%6,%7}, {%8,%9}, {%0,%1,%2,%3};"
        : "+f"(d[0]), "+f"(d[1]), "+f"(d[2]), "+f"(d[3])
        : "r"(a[0]), "r"(a[1]), "r"(a[2]), "r"(a[3]), "r"(b0), "r"(b1));
}

__device__ __forceinline__ void cp_async16(float* smem_dst, const float* gsrc) {
    unsigned s = (unsigned)__cvta_generic_to_shared(smem_dst);
    asm volatile("cp.async.cg.shared.global [%0], [%1], 16;\n" :: "r"(s), "l"(gsrc));
}

__global__ __launch_bounds__(128) void attn_kernel2()
{
    extern __shared__ float sm[];
    float* Qs = sm;                      // 128 x QSTRIDE (tf32-prerounded, scaled)
    float* Ks = sm + 128*QSTRIDE;        // 2 x 64 x KSTRIDE
    float* Vs = Ks + 2*64*KSTRIDE;       // 2 x 64 x VSTRIDE

    const int t  = threadIdx.x;
    const int w  = t >> 5;
    const int l  = t & 31;
    const int q4 = l & 3;      // quad position
    const int g  = l >> 2;     // group id (row within strip)
    const int qt = blockIdx.x, h = blockIdx.y, b = blockIdx.z;

    const size_t headoff = (size_t)(b*NH + h)*SEQ*HD;
    const float* Qg = g_Q + headoff + (size_t)qt*128*HD;
    const float* Kg = g_K + headoff;
    const float* Vg = g_V + headoff;

    // Load Q tile: scale by 1/8, pre-round to tf32, store padded.
    for (int i = t; i < 128*16; i += 128) {
        int r = i >> 4, c = (i & 15) << 2;
        float4 v = *(const float4*)(Qg + (size_t)r*HD + c);
        float4 o;
        o.x = __uint_as_float(f2tf(v.x * 0.125f));
        o.y = __uint_as_float(f2tf(v.y * 0.125f));
        o.z = __uint_as_float(f2tf(v.z * 0.125f));
        o.w = __uint_as_float(f2tf(v.w * 0.125f));
        *(float4*)(Qs + r*QSTRIDE + c) = o;
    }

#define ISSUE_TILE(KT, BUF) do {                                          \
        const float* kp_ = Kg + (size_t)(KT)*64*HD;                        \
        const float* vp_ = Vg + (size_t)(KT)*64*HD;                        \
        float* kd_ = Ks + (BUF)*64*KSTRIDE;                                \
        float* vd_ = Vs + (BUF)*64*VSTRIDE;                                \
        for (int i_ = t; i_ < 1024; i_ += 128) {                           \
            int r_ = i_ >> 4, c_ = (i_ & 15) << 2;                         \
            cp_async16(kd_ + r_*KSTRIDE + c_, kp_ + (size_t)r_*HD + c_);   \
            cp_async16(vd_ + r_*VSTRIDE + c_, vp_ + (size_t)r_*HD + c_);   \
        }                                                                  \
        asm volatile("cp.async.commit_group;\n");                          \
    } while (0)

    // register state
    float of[2][8][4];
#pragma unroll
    for (int s = 0; s < 2; s++)
#pragma unroll
        for (int nf = 0; nf < 8; nf++)
#pragma unroll
            for (int e = 0; e < 4; e++) of[s][nf][e] = 0.f;
    float mrun[2][2] = {{-1e30f, -1e30f}, {-1e30f, -1e30f}};
    float lrun[2][2] = {{0.f, 0.f}, {0.f, 0.f}};

    const int rbase = w * 32;

    ISSUE_TILE(0, 0);

    const int NT = SEQ / 64;   // 64 k-tiles
    for (int kt = 0; kt < NT; kt++) {
        const int buf = kt & 1;
        if (kt + 1 < NT) {
            ISSUE_TILE(kt + 1, buf ^ 1);
            asm volatile("cp.async.wait_group 1;\n");
        } else {
            asm volatile("cp.async.wait_group 0;\n");
        }
        __syncthreads();

        const float* kb_ = Ks + buf*64*KSTRIDE;
        const float* vb_ = Vs + buf*64*VSTRIDE;

        // ---- S = Q K^T (per-warp 32x64, registers) ----
        float sf[2][8][4];
#pragma unroll
        for (int s = 0; s < 2; s++)
#pragma unroll
            for (int nf = 0; nf < 8; nf++)
#pragma unroll
                for (int e = 0; e < 4; e++) sf[s][nf][e] = 0.f;

#pragma unroll
        for (int ks = 0; ks < 8; ks++) {
            unsigned qa[2][4];
#pragma unroll
            for (int s = 0; s < 2; s++) {
                const float* qrow = Qs + (rbase + s*16 + g)*QSTRIDE + ks*8;
                qa[s][0] = __float_as_uint(qrow[q4]);
                qa[s][1] = __float_as_uint(qrow[8*QSTRIDE + q4]);
                qa[s][2] = __float_as_uint(qrow[q4 + 4]);
                qa[s][3] = __float_as_uint(qrow[8*QSTRIDE + q4 + 4]);
            }
#pragma unroll
            for (int nf = 0; nf < 8; nf++) {
                const float* krow = kb_ + (nf*8 + g)*KSTRIDE + ks*8;
                unsigned b0 = __float_as_uint(krow[q4]);      // RZ tf32 (HW truncation)
                unsigned b1 = __float_as_uint(krow[q4 + 4]);
                mma8(sf[0][nf], qa[0], b0, b1);
                mma8(sf[1][nf], qa[1], b0, b1);
            }
        }

        // ---- online softmax (registers) ----
#pragma unroll
        for (int s = 0; s < 2; s++) {
            float mx0 = -1e30f, mx1 = -1e30f;
#pragma unroll
            for (int nf = 0; nf < 8; nf++) {
                mx0 = fmaxf(mx0, fmaxf(sf[s][nf][0], sf[s][nf][1]));
                mx1 = fmaxf(mx1, fmaxf(sf[s][nf][2], sf[s][nf][3]));
            }
            mx0 = fmaxf(mx0, __shfl_xor_sync(0xffffffffu, mx0, 1));
            mx0 = fmaxf(mx0, __shfl_xor_sync(0xffffffffu, mx0, 2));
            mx1 = fmaxf(mx1, __shfl_xor_sync(0xffffffffu, mx1, 1));
            mx1 = fmaxf(mx1, __shfl_xor_sync(0xffffffffu, mx1, 2));
            float mn0 = fmaxf(mrun[s][0], mx0);
            float mn1 = fmaxf(mrun[s][1], mx1);
            float a0 = __expf(mrun[s][0] - mn0);
            float a1 = __expf(mrun[s][1] - mn1);
            mrun[s][0] = mn0; mrun[s][1] = mn1;
            float sum0 = 0.f, sum1 = 0.f;
#pragma unroll
            for (int nf = 0; nf < 8; nf++) {
                float p0 = __expf(sf[s][nf][0] - mn0);
                float p1 = __expf(sf[s][nf][1] - mn0);
                float p2 = __expf(sf[s][nf][2] - mn1);
                float p3 = __expf(sf[s][nf][3] - mn1);
                sum0 += p0 + p1; sum1 += p2 + p3;
                sf[s][nf][0] = p0; sf[s][nf][1] = p1;
                sf[s][nf][2] = p2; sf[s][nf][3] = p3;
            }
            sum0 += __shfl_xor_sync(0xffffffffu, sum0, 1);
            sum0 += __shfl_xor_sync(0xffffffffu, sum0, 2);
            sum1 += __shfl_xor_sync(0xffffffffu, sum1, 1);
            sum1 += __shfl_xor_sync(0xffffffffu, sum1, 2);
            lrun[s][0] = lrun[s][0]*a0 + sum0;
            lrun[s][1] = lrun[s][1]*a1 + sum1;
#pragma unroll
            for (int nf = 0; nf < 8; nf++) {
                of[s][nf][0] *= a0; of[s][nf][1] *= a0;
                of[s][nf][2] *= a1; of[s][nf][3] *= a1;
            }
        }

        // ---- O += P V (P accum->A operand via quad shuffles) ----
        const int src0 = (l & ~3) | (q4 >> 1);
        const bool odd = (q4 & 1);
#pragma unroll
        for (int ks = 0; ks < 8; ks++) {
            unsigned pa[2][4];
#pragma unroll
            for (int s = 0; s < 2; s++) {
                float c0 = sf[s][ks][0], c1 = sf[s][ks][1];
                float c2 = sf[s][ks][2], c3 = sf[s][ks][3];
                float v00 = __shfl_sync(0xffffffffu, c0, src0);
                float v01 = __shfl_sync(0xffffffffu, c1, src0);
                float v10 = __shfl_sync(0xffffffffu, c0, src0 + 2);
                float v11 = __shfl_sync(0xffffffffu, c1, src0 + 2);
                float w00 = __shfl_sync(0xffffffffu, c2, src0);
                float w01 = __shfl_sync(0xffffffffu, c3, src0);
                float w10 = __shfl_sync(0xffffffffu, c2, src0 + 2);
                float w11 = __shfl_sync(0xffffffffu, c3, src0 + 2);
                pa[s][0] = f2tf(odd ? v01 : v00);
                pa[s][1] = f2tf(odd ? w01 : w00);
                pa[s][2] = f2tf(odd ? v11 : v10);
                pa[s][3] = f2tf(odd ? w11 : w10);
            }
#pragma unroll
            for (int nf = 0; nf < 8; nf++) {
                const float* vrow = vb_ + (ks*8 + q4)*VSTRIDE + nf*8 + g;
                unsigned b0 = f2tf(vrow[0]);
                unsigned b1 = f2tf(vrow[4*VSTRIDE]);
                mma8(of[0][nf], pa[0], b0, b1);
                mma8(of[1][nf], pa[1], b0, b1);
            }
        }
        __syncthreads();   // all warps done with buf before it is refilled
    }

    // ---- epilogue: normalize rows, write merged heads [B,S,D] ----
#pragma unroll
    for (int s = 0; s < 2; s++) {
        float inv0 = 1.f / lrun[s][0];
        float inv1 = 1.f / lrun[s][1];
        int r0 = qt*128 + rbase + s*16 + g;
#pragma unroll
        for (int nf = 0; nf < 8; nf++) {
            int col = h*64 + nf*8 + 2*q4;
            float2 p0; p0.x = of[s][nf][0]*inv0; p0.y = of[s][nf][1]*inv0;
            float2 p1; p1.x = of[s][nf][2]*inv1; p1.y = of[s][nf][3]*inv1;
            *(float2*)(g_AO + ((size_t)b*SEQ + r0    )*DIM + col) = p0;
            *(float2*)(g_AO + ((size_t)b*SEQ + r0 + 8)*DIM + col) = p1;
        }
    }
}

// ---------------------------------------------------------------------------
// Output projection: g_AO [8192,768] x Wo [768,768] + bo -> d_out
// ---------------------------------------------------------------------------
__global__ __launch_bounds__(256) void gemm_o_kernel(
    const float* __restrict__ Wo, const float* __restrict__ bo,
    float* __restrict__ out)
{
    __shared__ float As[64*32];
    __shared__ float Bs[32*64];
    __shared__ float Cs[64*64];

    const int t = threadIdx.x;
    const int warp = t >> 5;
    const int wr = warp >> 1;
    const int wc = (warp & 1) * 2;
    const int n0 = blockIdx.x * 64;
    const int m0 = blockIdx.y * 64;
    const float* A = g_AO;

    FragC c0, c1;
    wmma::fill_fragment(c0, 0.f);
    wmma::fill_fragment(c1, 0.f);

    for (int k0 = 0; k0 < DIM; k0 += 32) {
        for (int i = t; i < 512; i += 256) {
            int r = i >> 3, c4 = (i & 7) * 4;
            *(float4*)(As + r*32 + c4) =
                *(const float4*)(A + (size_t)(m0 + r)*DIM + k0 + c4);
        }
        for (int i = t; i < 512; i += 256) {
            int r = i >> 4, c4 = (i & 15) * 4;
            *(float4*)(Bs + r*64 + c4) =
                *(const float4*)(Wo + (size_t)(k0 + r)*DIM + n0 + c4);
        }
        __syncthreads();
#pragma unroll
        for (int kk = 0; kk < 4; kk++) {
            FragA a; FragB b0, b1;
            wmma::load_matrix_sync(a, As + wr*16*32 + kk*8, 32);
            conv_tf32(a);
            wmma::load_matrix_sync(b0, Bs + kk*8*64 + wc*16, 64);
            conv_tf32(b0);
            wmma::load_matrix_sync(b1, Bs + kk*8*64 + (wc + 1)*16, 64);
            conv_tf32(b1);
            wmma::mma_sync(c0, a, b0, c0);
            wmma::mma_sync(c1, a, b1, c1);
        }
        __syncthreads();
    }

    wmma::store_matrix_sync(Cs + wr*16*64 + wc*16,       c0, 64, wmma::mem_row_major);
    wmma::store_matrix_sync(Cs + wr*16*64 + (wc + 1)*16, c1, 64, wmma::mem_row_major);
    __syncthreads();

    for (int i = t; i < 4096; i += 256) {
        int r = i >> 6, c = i & 63;
        int m = m0 + r, nn = n0 + c;
        out[(size_t)m*DIM + nn] = Cs[r*64 + c] + bo[nn];
    }
}

// ---------------------------------------------------------------------------
extern "C" void kernel_launch(void* const* d_in, const int* in_sizes, int n_in,
                              void* d_out, int out_size)
{
    (void)in_sizes; (void)n_in; (void)out_size;
    const float* x  = (const float*)d_in[0];
    const float* Wq = (const float*)d_in[1];
    const float* bq = (const float*)d_in[2];
    const float* Wk = (const float*)d_in[3];
    const float* bk = (const float*)d_in[4];
    const float* Wv = (const float*)d_in[5];
    const float* bv = (const float*)d_in[6];
    const float* Wo = (const float*)d_in[7];
    const float* bo = (const float*)d_in[8];
    float* out = (float*)d_out;

    cudaFuncSetAttribute(attn_kernel2,
                         cudaFuncAttributeMaxDynamicSharedMemorySize,
                         ATTN2_SMEM_BYTES);

    gemm_qkv_kernel<<<dim3(36, 128), 256>>>(x, Wq, bq, Wk, bk, Wv, bv);
    attn_kernel2<<<dim3(SEQ/128, NH, BATCH), 128, ATTN2_SMEM_BYTES>>>();
    gemm_o_kernel<<<dim3(12, 128), 256>>>(Wo, bo, out);
}

// round 3
// speedup vs baseline: 5.1796x; 1.9859x over previous
#include <cuda_runtime.h>
#include <cstdint>

#define BATCH 2
#define SEQ 4096
#define DIM 768
#define NH 12
#define HD 64
#define ROWS (BATCH*SEQ)

// Scratch (allocation-free rule: __device__ globals)
__device__ float g_Q[(size_t)BATCH*NH*SEQ*HD];
__device__ float g_K[(size_t)BATCH*NH*SEQ*HD];
__device__ float g_V[(size_t)BATCH*NH*SEQ*HD];
__device__ float g_AO[(size_t)ROWS*DIM];
__device__ float g_Xr[(size_t)ROWS*DIM];          // X pre-rounded to tf32
__device__ float g_Wt[(size_t)4*DIM*DIM];         // Wq,Wk,Wv,Wo transposed [n][k], tf32

__device__ __forceinline__ unsigned f2tf(float f) {
    unsigned u;
    asm("cvt.rna.tf32.f32 %0, %1;" : "=r"(u) : "f"(f));
    return u;
}

__device__ __forceinline__ void mma8(float d[4], const unsigned a[4],
                                     unsigned b0, unsigned b1) {
    asm volatile(
        "mma.sync.aligned.m16n8k8.row.col.f32.tf32.tf32.f32 "
        "{%0,%1,%2,%3}, {%4,%5,%6,%7}, {%8,%9}, {%0,%1,%2,%3};"
        : "+f"(d[0]), "+f"(d[1]), "+f"(d[2]), "+f"(d[3])
        : "r"(a[0]), "r"(a[1]), "r"(a[2]), "r"(a[3]), "r"(b0), "r"(b1));
}

__device__ __forceinline__ void cp_async16(float* smem_dst, const float* gsrc) {
    unsigned s = (unsigned)__cvta_generic_to_shared(smem_dst);
    asm volatile("cp.async.cg.shared.global [%0], [%1], 16;\n" :: "r"(s), "l"(gsrc));
}

// ---------------------------------------------------------------------------
// Prep kernels: round X to tf32; transpose+round the 4 weight matrices.
// ---------------------------------------------------------------------------
__global__ __launch_bounds__(256) void round_x_kernel(const float* __restrict__ X)
{
    size_t i = ((size_t)blockIdx.x*256 + threadIdx.x) * 4;
    float4 v = *(const float4*)(X + i);
    float4 o;
    o.x = __uint_as_float(f2tf(v.x));
    o.y = __uint_as_float(f2tf(v.y));
    o.z = __uint_as_float(f2tf(v.z));
    o.w = __uint_as_float(f2tf(v.w));
    *(float4*)(g_Xr + i) = o;
}

__global__ __launch_bounds__(256) void transpose_w_kernel(
    const float* __restrict__ Wq, const float* __restrict__ Wk,
    const float* __restrict__ Wv, const float* __restrict__ Wo)
{
    __shared__ float ts[32][33];
    const float* W = (blockIdx.z == 0) ? Wq : (blockIdx.z == 1) ? Wk
                   : (blockIdx.z == 2) ? Wv : Wo;
    float* Wt = g_Wt + (size_t)blockIdx.z*DIM*DIM;
    int tx = threadIdx.x & 31, ty = threadIdx.x >> 5;   // 32 x 8
    int bx = blockIdx.x * 32, by = blockIdx.y * 32;
#pragma unroll
    for (int i = 0; i < 32; i += 8)
        ts[ty + i][tx] = W[(size_t)(by + ty + i)*DIM + bx + tx];
    __syncthreads();
#pragma unroll
    for (int i = 0; i < 32; i += 8)
        Wt[(size_t)(bx + ty + i)*DIM + by + tx] =
            __uint_as_float(f2tf(ts[tx][ty + i]));
}

// ---------------------------------------------------------------------------
// Raw-mma GEMM: C[128x128 tile] = A[8192,768] x Wt^T + bias
//   MODE 0: QKV — blockIdx.z selects matrix; scatter to g_Q/g_K/g_V [B,H,S,64]
//           (Q additionally scaled by 0.125), all values tf32-pre-rounded.
//   MODE 1: O-proj — write fp32 + bias to `out`.
// 256 threads = 8 warps (4m x 2n), warp tile 32x64, BK=32, cp.async 2-stage.
// ---------------------------------------------------------------------------
#define GSTR 36
#define GEMM_SMEM_BYTES (2*(128*GSTR + 128*GSTR)*4)

template<int MODE>
__global__ __launch_bounds__(256) void gemm128_kernel(
    const float* __restrict__ A, const float* __restrict__ Wt0,
    const float* __restrict__ bq, const float* __restrict__ bk,
    const float* __restrict__ bv, float* __restrict__ out)
{
    extern __shared__ float sm[];
    float* As = sm;                    // 2 x 128 x GSTR
    float* Bs = sm + 2*128*GSTR;       // 2 x 128 x GSTR

    const int t = threadIdx.x;
    const int w = t >> 5, l = t & 31;
    const int g = l >> 2, q4 = l & 3;
    const int m0 = blockIdx.y * 128;
    const int n0 = blockIdx.x * 128;
    const int wsel = (MODE == 0) ? blockIdx.z : 0;
    const float* Wt = Wt0 + (size_t)wsel*DIM*DIM;
    const float* bias = (MODE == 1) ? bq : ((wsel == 0) ? bq : (wsel == 1) ? bk : bv);

    const int m0w = (w >> 1) * 32;
    const int n0w = (w & 1) * 64;

#define G_ISSUE(KT, BUF) do {                                                  \
        int k0_ = (KT) * 32;                                                   \
        float* ad_ = As + (BUF)*128*GSTR;                                      \
        float* bd_ = Bs + (BUF)*128*GSTR;                                      \
        for (int i_ = t; i_ < 1024; i_ += 256) {                               \
            int r_ = i_ >> 3, c_ = (i_ & 7) << 2;                              \
            cp_async16(ad_ + r_*GSTR + c_, A  + (size_t)(m0 + r_)*DIM + k0_ + c_); \
            cp_async16(bd_ + r_*GSTR + c_, Wt + (size_t)(n0 + r_)*DIM + k0_ + c_); \
        }                                                                       \
        asm volatile("cp.async.commit_group;\n");                               \
    } while (0)

    float acc[2][8][4];
#pragma unroll
    for (int s = 0; s < 2; s++)
#pragma unroll
        for (int nf = 0; nf < 8; nf++)
#pragma unroll
            for (int e = 0; e < 4; e++) acc[s][nf][e] = 0.f;

    G_ISSUE(0, 0);

    const int NKT = DIM / 32;    // 24
    for (int kt = 0; kt < NKT; kt++) {
        const int buf = kt & 1;
        if (kt + 1 < NKT) {
            G_ISSUE(kt + 1, buf ^ 1);
            asm volatile("cp.async.wait_group 1;\n");
        } else {
            asm volatile("cp.async.wait_group 0;\n");
        }
        __syncthreads();

        const float* a_ = As + buf*128*GSTR;
        const float* b_ = Bs + buf*128*GSTR;

#pragma unroll
        for (int ks = 0; ks < 4; ks++) {
            unsigned af[2][4];
#pragma unroll
            for (int s = 0; s < 2; s++) {
                const float* arow = a_ + (m0w + s*16 + g)*GSTR + ks*8;
                af[s][0] = __float_as_uint(arow[q4]);
                af[s][1] = __float_as_uint(arow[8*GSTR + q4]);
                af[s][2] = __float_as_uint(arow[q4 + 4]);
                af[s][3] = __float_as_uint(arow[8*GSTR + q4 + 4]);
            }
#pragma unroll
            for (int nf = 0; nf < 8; nf++) {
                const float* brow = b_ + (n0w + nf*8 + g)*GSTR + ks*8;
                unsigned b0 = __float_as_uint(brow[q4]);
                unsigned b1 = __float_as_uint(brow[q4 + 4]);
                mma8(acc[0][nf], af[0], b0, b1);
                mma8(acc[1][nf], af[1], b0, b1);
            }
        }
        __syncthreads();
    }

    // epilogue
#pragma unroll
    for (int s = 0; s < 2; s++) {
#pragma unroll
        for (int nf = 0; nf < 8; nf++) {
            int m  = m0 + m0w + s*16 + g;
            int nn = n0 + n0w + nf*8 + 2*q4;
            float v0 = acc[s][nf][0] + bias[nn];
            float v1 = acc[s][nf][1] + bias[nn + 1];
            float v2 = acc[s][nf][2] + bias[nn];
            float v3 = acc[s][nf][3] + bias[nn + 1];
            if (MODE == 1) {
                float2 p0; p0.x = v0; p0.y = v1;
                float2 p1; p1.x = v2; p1.y = v3;
                *(float2*)(out + (size_t)m*DIM + nn)       = p0;
                *(float2*)(out + (size_t)(m + 8)*DIM + nn) = p1;
            } else {
                float sc = (wsel == 0) ? 0.125f : 1.0f;
                float* dst = (wsel == 0) ? g_Q : (wsel == 1) ? g_K : g_V;
                int bb = m >> 12, sq = m & 4095;
                int hh = nn >> 6, d = nn & 63;
                size_t base = ((size_t)(bb*NH + hh)*SEQ + sq)*HD + d;
                float2 p0, p1;
                p0.x = __uint_as_float(f2tf(v0 * sc));
                p0.y = __uint_as_float(f2tf(v1 * sc));
                p1.x = __uint_as_float(f2tf(v2 * sc));
                p1.y = __uint_as_float(f2tf(v3 * sc));
                *(float2*)(dst + base)          = p0;
                *(float2*)(dst + base + 8*HD)   = p1;
            }
        }
    }
}

// ---------------------------------------------------------------------------
// Flash attention: register-resident mma.sync m16n8k8 tf32.
// Q/K/V arrive tf32-pre-rounded (Q pre-scaled by 1/8) -> no CVT in mainloop.
// ---------------------------------------------------------------------------
#define QSTRIDE 68
#define KSTRIDE 68
#define VSTRIDE 72
#define ATTN2_SMEM_BYTES ((128*QSTRIDE + 2*64*KSTRIDE + 2*64*VSTRIDE) * 4)

__global__ __launch_bounds__(128) void attn_kernel2()
{
    extern __shared__ float sm[];
    float* Qs = sm;                      // 128 x QSTRIDE
    float* Ks = sm + 128*QSTRIDE;        // 2 x 64 x KSTRIDE
    float* Vs = Ks + 2*64*KSTRIDE;       // 2 x 64 x VSTRIDE

    const int t  = threadIdx.x;
    const int w  = t >> 5;
    const int l  = t & 31;
    const int q4 = l & 3;
    const int g  = l >> 2;
    const int qt = blockIdx.x, h = blockIdx.y, b = blockIdx.z;

    const size_t headoff = (size_t)(b*NH + h)*SEQ*HD;
    const float* Qg = g_Q + headoff + (size_t)qt*128*HD;
    const float* Kg = g_K + headoff;
    const float* Vg = g_V + headoff;

    for (int i = t; i < 128*16; i += 128) {
        int r = i >> 4, c = (i & 15) << 2;
        *(float4*)(Qs + r*QSTRIDE + c) = *(const float4*)(Qg + (size_t)r*HD + c);
    }

#define ISSUE_TILE(KT, BUF) do {                                          \
        const float* kp_ = Kg + (size_t)(KT)*64*HD;                        \
        const float* vp_ = Vg + (size_t)(KT)*64*HD;                        \
        float* kd_ = Ks + (BUF)*64*KSTRIDE;                                \
        float* vd_ = Vs + (BUF)*64*VSTRIDE;                                \
        for (int i_ = t; i_ < 1024; i_ += 128) {                           \
            int r_ = i_ >> 4, c_ = (i_ & 15) << 2;                         \
            cp_async16(kd_ + r_*KSTRIDE + c_, kp_ + (size_t)r_*HD + c_);   \
            cp_async16(vd_ + r_*VSTRIDE + c_, vp_ + (size_t)r_*HD + c_);   \
        }                                                                  \
        asm volatile("cp.async.commit_group;\n");                          \
    } while (0)

    float of[2][8][4];
#pragma unroll
    for (int s = 0; s < 2; s++)
#pragma unroll
        for (int nf = 0; nf < 8; nf++)
#pragma unroll
            for (int e = 0; e < 4; e++) of[s][nf][e] = 0.f;
    float mrun[2][2] = {{-1e30f, -1e30f}, {-1e30f, -1e30f}};
    float lrun[2][2] = {{0.f, 0.f}, {0.f, 0.f}};

    const int rbase = w * 32;

    ISSUE_TILE(0, 0);

    const int NT = SEQ / 64;
    for (int kt = 0; kt < NT; kt++) {
        const int buf = kt & 1;
        if (kt + 1 < NT) {
            ISSUE_TILE(kt + 1, buf ^ 1);
            asm volatile("cp.async.wait_group 1;\n");
        } else {
            asm volatile("cp.async.wait_group 0;\n");
        }
        __syncthreads();

        const float* kb_ = Ks + buf*64*KSTRIDE;
        const float* vb_ = Vs + buf*64*VSTRIDE;

        // ---- S = Q K^T ----
        float sf[2][8][4];
#pragma unroll
        for (int s = 0; s < 2; s++)
#pragma unroll
            for (int nf = 0; nf < 8; nf++)
#pragma unroll
                for (int e = 0; e < 4; e++) sf[s][nf][e] = 0.f;

#pragma unroll
        for (int ks = 0; ks < 8; ks++) {
            unsigned qa[2][4];
#pragma unroll
            for (int s = 0; s < 2; s++) {
                const float* qrow = Qs + (rbase + s*16 + g)*QSTRIDE + ks*8;
                qa[s][0] = __float_as_uint(qrow[q4]);
                qa[s][1] = __float_as_uint(qrow[8*QSTRIDE + q4]);
                qa[s][2] = __float_as_uint(qrow[q4 + 4]);
                qa[s][3] = __float_as_uint(qrow[8*QSTRIDE + q4 + 4]);
            }
#pragma unroll
            for (int nf = 0; nf < 8; nf++) {
                const float* krow = kb_ + (nf*8 + g)*KSTRIDE + ks*8;
                unsigned b0 = __float_as_uint(krow[q4]);
                unsigned b1 = __float_as_uint(krow[q4 + 4]);
                mma8(sf[0][nf], qa[0], b0, b1);
                mma8(sf[1][nf], qa[1], b0, b1);
            }
        }

        // ---- online softmax ----
#pragma unroll
        for (int s = 0; s < 2; s++) {
            float mx0 = -1e30f, mx1 = -1e30f;
#pragma unroll
            for (int nf = 0; nf < 8; nf++) {
                mx0 = fmaxf(mx0, fmaxf(sf[s][nf][0], sf[s][nf][1]));
                mx1 = fmaxf(mx1, fmaxf(sf[s][nf][2], sf[s][nf][3]));
            }
            mx0 = fmaxf(mx0, __shfl_xor_sync(0xffffffffu, mx0, 1));
            mx0 = fmaxf(mx0, __shfl_xor_sync(0xffffffffu, mx0, 2));
            mx1 = fmaxf(mx1, __shfl_xor_sync(0xffffffffu, mx1, 1));
            mx1 = fmaxf(mx1, __shfl_xor_sync(0xffffffffu, mx1, 2));
            float mn0 = fmaxf(mrun[s][0], mx0);
            float mn1 = fmaxf(mrun[s][1], mx1);
            float a0 = __expf(mrun[s][0] - mn0);
            float a1 = __expf(mrun[s][1] - mn1);
            mrun[s][0] = mn0; mrun[s][1] = mn1;
            float sum0 = 0.f, sum1 = 0.f;
#pragma unroll
            for (int nf = 0; nf < 8; nf++) {
                float p0 = __expf(sf[s][nf][0] - mn0);
                float p1 = __expf(sf[s][nf][1] - mn0);
                float p2 = __expf(sf[s][nf][2] - mn1);
                float p3 = __expf(sf[s][nf][3] - mn1);
                sum0 += p0 + p1; sum1 += p2 + p3;
                sf[s][nf][0] = p0; sf[s][nf][1] = p1;
                sf[s][nf][2] = p2; sf[s][nf][3] = p3;
            }
            sum0 += __shfl_xor_sync(0xffffffffu, sum0, 1);
            sum0 += __shfl_xor_sync(0xffffffffu, sum0, 2);
            sum1 += __shfl_xor_sync(0xffffffffu, sum1, 1);
            sum1 += __shfl_xor_sync(0xffffffffu, sum1, 2);
            lrun[s][0] = lrun[s][0]*a0 + sum0;
            lrun[s][1] = lrun[s][1]*a1 + sum1;
#pragma unroll
            for (int nf = 0; nf < 8; nf++) {
                of[s][nf][0] *= a0; of[s][nf][1] *= a0;
                of[s][nf][2] *= a1; of[s][nf][3] *= a1;
            }
        }

        // ---- O += P V ----
        const int src0 = (l & ~3) | (q4 >> 1);
        const bool odd = (q4 & 1);
#pragma unroll
        for (int ks = 0; ks < 8; ks++) {
            unsigned pa[2][4];
#pragma unroll
            for (int s = 0; s < 2; s++) {
                float c0 = sf[s][ks][0], c1 = sf[s][ks][1];
                float c2 = sf[s][ks][2], c3 = sf[s][ks][3];
                float v00 = __shfl_sync(0xffffffffu, c0, src0);
                float v01 = __shfl_sync(0xffffffffu, c1, src0);
                float v10 = __shfl_sync(0xffffffffu, c0, src0 + 2);
                float v11 = __shfl_sync(0xffffffffu, c1, src0 + 2);
                float w00 = __shfl_sync(0xffffffffu, c2, src0);
                float w01 = __shfl_sync(0xffffffffu, c3, src0);
                float w10 = __shfl_sync(0xffffffffu, c2, src0 + 2);
                float w11 = __shfl_sync(0xffffffffu, c3, src0 + 2);
                pa[s][0] = f2tf(odd ? v01 : v00);
                pa[s][1] = f2tf(odd ? w01 : w00);
                pa[s][2] = f2tf(odd ? v11 : v10);
                pa[s][3] = f2tf(odd ? w11 : w10);
            }
#pragma unroll
            for (int nf = 0; nf < 8; nf++) {
                const float* vrow = vb_ + (ks*8 + q4)*VSTRIDE + nf*8 + g;
                unsigned b0 = __float_as_uint(vrow[0]);
                unsigned b1 = __float_as_uint(vrow[4*VSTRIDE]);
                mma8(of[0][nf], pa[0], b0, b1);
                mma8(of[1][nf], pa[1], b0, b1);
            }
        }
        __syncthreads();
    }

    // ---- epilogue: normalize, round to tf32 for the O-proj, write [B,S,D] ----
#pragma unroll
    for (int s = 0; s < 2; s++) {
        float inv0 = 1.f / lrun[s][0];
        float inv1 = 1.f / lrun[s][1];
        int r0 = qt*128 + rbase + s*16 + g;
#pragma unroll
        for (int nf = 0; nf < 8; nf++) {
            int col = h*64 + nf*8 + 2*q4;
            float2 p0, p1;
            p0.x = __uint_as_float(f2tf(of[s][nf][0]*inv0));
            p0.y = __uint_as_float(f2tf(of[s][nf][1]*inv0));
            p1.x = __uint_as_float(f2tf(of[s][nf][2]*inv1));
            p1.y = __uint_as_float(f2tf(of[s][nf][3]*inv1));
            *(float2*)(g_AO + ((size_t)b*SEQ + r0    )*DIM + col) = p0;
            *(float2*)(g_AO + ((size_t)b*SEQ + r0 + 8)*DIM + col) = p1;
        }
    }
}

// ---------------------------------------------------------------------------
extern "C" void kernel_launch(void* const* d_in, const int* in_sizes, int n_in,
                              void* d_out, int out_size)
{
    (void)in_sizes; (void)n_in; (void)out_size;
    const float* x  = (const float*)d_in[0];
    const float* Wq = (const float*)d_in[1];
    const float* bq = (const float*)d_in[2];
    const float* Wk = (const float*)d_in[3];
    const float* bk = (const float*)d_in[4];
    const float* Wv = (const float*)d_in[5];
    const float* bv = (const float*)d_in[6];
    const float* Wo = (const float*)d_in[7];
    const float* bo = (const float*)d_in[8];
    float* out = (float*)d_out;

    cudaFuncSetAttribute(attn_kernel2,
                         cudaFuncAttributeMaxDynamicSharedMemorySize,
                         ATTN2_SMEM_BYTES);
    cudaFuncSetAttribute(gemm128_kernel<0>,
                         cudaFuncAttributeMaxDynamicSharedMemorySize,
                         GEMM_SMEM_BYTES);
    cudaFuncSetAttribute(gemm128_kernel<1>,
                         cudaFuncAttributeMaxDynamicSharedMemorySize,
                         GEMM_SMEM_BYTES);

    round_x_kernel<<<ROWS*DIM/(256*4), 256>>>(x);
    transpose_w_kernel<<<dim3(24, 24, 4), 256>>>(Wq, Wk, Wv, Wo);

    float* g_Wt_ptr;
    cudaGetSymbolAddress((void**)&g_Wt_ptr, g_Wt);
    float* g_Xr_ptr;
    cudaGetSymbolAddress((void**)&g_Xr_ptr, g_Xr);
    float* g_AO_ptr;
    cudaGetSymbolAddress((void**)&g_AO_ptr, g_AO);

    gemm128_kernel<0><<<dim3(6, 64, 3), 256, GEMM_SMEM_BYTES>>>(
        g_Xr_ptr, g_Wt_ptr, bq, bk, bv, nullptr);

    attn_kernel2<<<dim3(SEQ/128, NH, BATCH), 128, ATTN2_SMEM_BYTES>>>();

    gemm128_kernel<1><<<dim3(6, 64, 1), 256, GEMM_SMEM_BYTES>>>(
        g_AO_ptr, g_Wt_ptr + (size_t)3*DIM*DIM, bo, nullptr, nullptr, out);
}